// round 11
// baseline (speedup 1.0000x reference)
#include <cuda_runtime.h>
#include <cstdint>

#define Bb 16
#define Nn 16
#define Hh 512
#define Ww 512
#define HW  (Hh * Ww)
#define HW4 (HW / 4)                  // 65536 float4 per slice
#define THREADS 256
#define NG 2
#define NGROUPS (Nn / NG)             // 8
#define SPLIT 8
#define CHUNK_F4 (HW4 / SPLIT)        // 8192 float4 per tensor per block
#define ITER (CHUNK_F4 / THREADS)     // 32
#define GRID_S (Bb * NGROUPS * SPLIT) // 1024 stream blocks
#define BOX_BLOCKS 64                 // 4 boxes each, 2 warps per box
#define GRID_T (GRID_S + BOX_BLOCKS)  // 1088

__device__ float    g_ov[Bb * Nn];
__device__ float    g_it[Bb * Nn];
__device__ float    g_ts[Bb];
__device__ unsigned g_done;

__global__ void fused7_kernel(const float* __restrict__ masks,
                              const float* __restrict__ target,
                              const int*   __restrict__ boxes,
                              float*       __restrict__ out)
{
    const int tid = threadIdx.x;
    const int wid = tid >> 5;
    const int lid = tid & 31;
    const unsigned FULL = 0xFFFFFFFFu;
    __shared__ float s_red[THREADS / 32][3];

    if (blockIdx.x < GRID_S) {
        // ======= stream blocks: ov[2] + ts — pure streaming, no box logic =======
        const int blk  = blockIdx.x;
        const int b    = blk >> 6;          // / (NGROUPS*SPLIT) = /64
        const int rest = blk & 63;
        const int ng   = rest >> 3;         // 0..7
        const int sp   = rest & 7;          // 0..7

        const size_t coff = (size_t)sp * CHUNK_F4;
        const float4* __restrict__ tp = (const float4*)target + (size_t)b * HW4 + coff;
        const float4* __restrict__ p0 = (const float4*)masks + ((size_t)(b * Nn + ng * NG + 0)) * HW4 + coff;
        const float4* __restrict__ p1 = (const float4*)masks + ((size_t)(b * Nn + ng * NG + 1)) * HW4 + coff;

        float ov0 = 0.f, ov1 = 0.f, ts = 0.f;

        #pragma unroll 4
        for (int k = tid; k < CHUNK_F4; k += THREADS) {
            const float4 tv = tp[k];
            const float4 v0 = p0[k];
            const float4 v1 = p1[k];

            ts += (tv.x + tv.y) + (tv.z + tv.w);
            ov0 = fmaf(v0.x, tv.x, ov0); ov0 = fmaf(v0.y, tv.y, ov0);
            ov0 = fmaf(v0.z, tv.z, ov0); ov0 = fmaf(v0.w, tv.w, ov0);
            ov1 = fmaf(v1.x, tv.x, ov1); ov1 = fmaf(v1.y, tv.y, ov1);
            ov1 = fmaf(v1.z, tv.z, ov1); ov1 = fmaf(v1.w, tv.w, ov1);
        }

        float v[3] = {ov0, ov1, ts};
        #pragma unroll
        for (int q = 0; q < 3; q++) {
            #pragma unroll
            for (int off = 16; off > 0; off >>= 1)
                v[q] += __shfl_xor_sync(FULL, v[q], off);
        }
        if (lid == 0) {
            s_red[wid][0] = v[0]; s_red[wid][1] = v[1]; s_red[wid][2] = v[2];
        }
        __syncthreads();

        if (tid < 3) {
            float sum = 0.f;
            #pragma unroll
            for (int w = 0; w < THREADS / 32; w++) sum += s_red[w][tid];
            if (tid < 2) {
                atomicAdd(&g_ov[b * Nn + ng * NG + tid], sum);
            } else if (ng == 0) {     // ts counted once per (b, chunk)
                atomicAdd(&g_ts[b], sum);
            }
        }
    } else {
        // ======= box blocks: intersection, 2 warps per box, no syncs =======
        const int base_bn = (blockIdx.x - GRID_S) * 4;
        const int bn   = base_bn + (wid >> 1);   // warps {2j,2j+1} -> box j
        const int half = wid & 1;
        const int b    = bn >> 4;
        const int4 bx = __ldg((const int4*)boxes + bn);
        const float* __restrict__ t = target + (size_t)b * HW;

        float it = 0.f;
        for (int h = bx.y + half; h < bx.w; h += 2) {
            const float* row = t + h * Ww;
            for (int w = bx.x + lid; w < bx.z; w += 32)
                it += __ldg(row + w);
        }
        #pragma unroll
        for (int off = 16; off > 0; off >>= 1)
            it += __shfl_xor_sync(FULL, it, off);
        if (lid == 0) atomicAdd(&g_it[bn], it);   // exact integers: order-safe
    }

    __threadfence();
    __syncthreads();

    __shared__ unsigned s_last;
    if (tid == 0) s_last = atomicAdd(&g_done, 1u);
    __syncthreads();

    // ---- last block finalizes + resets (graph-replay safe) ----
    if (s_last == GRID_T - 1) {
        const int bn = tid;   // 0..255
        const float ovv = *(volatile float*)&g_ov[bn];
        const float itv = *(volatile float*)&g_it[bn];
        const float tsv = *(volatile float*)&g_ts[bn >> 4];
        const int4 bx = reinterpret_cast<const int4*>(boxes)[bn];
        const float area = (float)(bx.z - bx.x) * (float)(bx.w - bx.y);
        const float uni = area + tsv - itv;
        out[bn * 2 + 0] = ovv;
        out[bn * 2 + 1] = itv / (uni + 1e-8f);
        g_ov[bn] = 0.f;
        g_it[bn] = 0.f;
        if (bn < Bb) g_ts[bn] = 0.f;
        if (bn == 0) g_done = 0u;
    }
}

extern "C" void kernel_launch(void* const* d_in, const int* in_sizes, int n_in,
                              void* d_out, int out_size)
{
    const float* masks  = (const float*)d_in[0];   // (B,N,H,W) f32
    const float* target = (const float*)d_in[1];   // (B,H,W)   f32
    const int*   boxes  = (const int*)d_in[2];     // (B,N,4)   i32
    float* out = (float*)d_out;                    // (B,N,2)   f32

    fused7_kernel<<<GRID_T, THREADS>>>(masks, target, boxes, out);
}

// round 12
// speedup vs baseline: 6.1183x; 6.1183x over previous
#include <cuda_runtime.h>
#include <cstdint>

#define Bb 16
#define Nn 16
#define Hh 512
#define Ww 512
#define HW (Hh * Ww)
#define HW4 (HW / 4)        // 65536 float4 per (b,n) slice
#define W4 (Ww / 4)         // 128 float4 per row
#define THREADS 256
#define SPLIT 4
#define CHUNK (HW4 / SPLIT) // 16384 float4 per block
#define UB 4                // load batch
#define OUTER (CHUNK / (THREADS * UB))  // 16
#define GRID (Bb * Nn * SPLIT)          // 1024

__device__ float    g_ov[Bb * Nn];
__device__ float    g_it[Bb * Nn];
__device__ float    g_ts[Bb * Nn];
__device__ unsigned g_done;

__global__ __launch_bounds__(THREADS)
void stream_kernel(const float* __restrict__ masks,
                   const float* __restrict__ target,
                   const int*   __restrict__ boxes,
                   float*       __restrict__ out)
{
    const int blk   = blockIdx.x;          // 0..1023
    const int bn    = blk / SPLIT;         // 0..255
    const int split = blk % SPLIT;
    const int b     = bn >> 4;

    const int tid = threadIdx.x;
    const int base = split * CHUNK;

    const float4* __restrict__ mp = (const float4*)masks + (size_t)bn * HW4 + base + tid;
    const float4* __restrict__ tp = (const float4*)target + (size_t)b  * HW4 + base + tid;

    const int4 box = reinterpret_cast<const int4*>(boxes)[bn];
    const int x1 = box.x, y1 = box.y, x2 = box.z, y2 = box.w;

    // k-invariant column selectors for this thread's float4 lane
    const int w0 = (tid & (W4 - 1)) << 2;
    const float c0 = (w0     >= x1 && w0     < x2) ? 1.f : 0.f;
    const float c1 = (w0 + 1 >= x1 && w0 + 1 < x2) ? 1.f : 0.f;
    const float c2 = (w0 + 2 >= x1 && w0 + 2 < x2) ? 1.f : 0.f;
    const float c3 = (w0 + 3 >= x1 && w0 + 3 < x2) ? 1.f : 0.f;

    // row index: advances by 2 per k-step (stride 256 float4 = 2 rows)
    int h = (base >> 7) + (tid >> 7);

    float ov = 0.f, ts = 0.f, it = 0.f;

    for (int kk = 0; kk < OUTER; kk++) {
        float4 mv[UB], tv[UB];
        #pragma unroll
        for (int u = 0; u < UB; u++) {
            mv[u] = __ldcs(mp + u * THREADS);   // streaming, evict-first: dead after use
            tv[u] = __ldg(tp + u * THREADS);    // L2-resident, reused by 16 bn
        }
        mp += UB * THREADS;
        tp += UB * THREADS;

        #pragma unroll
        for (int u = 0; u < UB; u++) {
            ov = fmaf(mv[u].x, tv[u].x, ov);
            ov = fmaf(mv[u].y, tv[u].y, ov);
            ov = fmaf(mv[u].z, tv[u].z, ov);
            ov = fmaf(mv[u].w, tv[u].w, ov);

            ts += (tv[u].x + tv[u].y) + (tv[u].z + tv[u].w);

            const int hu = h + 2 * u;
            if (hu >= y1 && hu < y2) {
                float s;
                s = fmaf(c0, tv[u].x, 0.f);
                s = fmaf(c1, tv[u].y, s);
                s = fmaf(c2, tv[u].z, s);
                s = fmaf(c3, tv[u].w, s);
                it += s;
            }
        }
        h += 2 * UB;
    }

    // ---- single block reduction ----
    const unsigned FULL = 0xFFFFFFFFu;
    #pragma unroll
    for (int off = 16; off > 0; off >>= 1) {
        ov += __shfl_xor_sync(FULL, ov, off);
        ts += __shfl_xor_sync(FULL, ts, off);
        it += __shfl_xor_sync(FULL, it, off);
    }

    __shared__ float s_ov[THREADS / 32];
    __shared__ float s_ts[THREADS / 32];
    __shared__ float s_it[THREADS / 32];
    const int wid = tid >> 5;
    const int lid = tid & 31;
    if (lid == 0) { s_ov[wid] = ov; s_ts[wid] = ts; s_it[wid] = it; }
    __syncthreads();

    if (tid < 3) {
        float sum = 0.f;
        if (tid == 0) {
            #pragma unroll
            for (int w = 0; w < THREADS / 32; w++) sum += s_ov[w];
            atomicAdd(&g_ov[bn], sum);
        } else if (tid == 1) {
            #pragma unroll
            for (int w = 0; w < THREADS / 32; w++) sum += s_it[w];
            atomicAdd(&g_it[bn], sum);
        } else {
            #pragma unroll
            for (int w = 0; w < THREADS / 32; w++) sum += s_ts[w];
            atomicAdd(&g_ts[bn], sum);
        }
    }
    __threadfence();
    __syncthreads();

    __shared__ unsigned s_last;
    if (tid == 0) s_last = atomicAdd(&g_done, 1u);
    __syncthreads();

    // ---- last block finalizes + resets (graph-replay safe) ----
    if (s_last == GRID - 1) {
        const int j = tid;                     // 0..255 = one per bn
        const float ovv = *(volatile float*)&g_ov[j];
        const float itv = *(volatile float*)&g_it[j];
        const float tsv = *(volatile float*)&g_ts[j];
        const int4 bx = reinterpret_cast<const int4*>(boxes)[j];
        const float area = (float)(bx.z - bx.x) * (float)(bx.w - bx.y);
        const float uni = area + tsv - itv;
        out[j * 2 + 0] = ovv;
        out[j * 2 + 1] = itv / (uni + 1e-8f);
        g_ov[j] = 0.f;
        g_it[j] = 0.f;
        g_ts[j] = 0.f;
        if (j == 0) g_done = 0u;
    }
}

extern "C" void kernel_launch(void* const* d_in, const int* in_sizes, int n_in,
                              void* d_out, int out_size)
{
    const float* masks  = (const float*)d_in[0];   // (B,N,H,W) f32
    const float* target = (const float*)d_in[1];   // (B,H,W)   f32
    const int*   boxes  = (const int*)d_in[2];     // (B,N,4)   i32
    float* out = (float*)d_out;                    // (B,N,2)   f32

    stream_kernel<<<GRID, THREADS>>>(masks, target, boxes, out);
}